// round 1
// baseline (speedup 1.0000x reference)
#include <cuda_runtime.h>
#include <cuda_bf16.h>

// Problem:
//  x  : (1, 64, 28, 28)  fp32   -> view as (2 groups o, 32 ch j, 28 n, 28 m)
//  w1 : (128, 9)         fp32
//  w2 : (32, 7, 9)       fp32
//  out: (1, 256, 28, 28) fp32,  channel = o*128 + c, rolled +1 along height.
//
//  t4[o,n,m,i] = sum_{j,k} x[o*32+j, n, m+k-3] * w2[j,k,i]       (zero-pad width)
//  out[o,c,(n+1)%28,m] = sum_i w1[c,i] * t4[o,n,m,i]

#define NTHREADS 256

__global__ __launch_bounds__(NTHREADS)
void fused_unfold_einsum_kernel(const float* __restrict__ x,
                                const float* __restrict__ w1,
                                const float* __restrict__ w2,
                                float* __restrict__ out) {
    // Shared staging
    __shared__ float xs[32][34];        // padded width: m in [-3, 31) -> mm in [0,34)
    __shared__ float w2t[9 * 32 * 7];   // transposed: [i][j*7+k]
    __shared__ float w1s[128 * 9];      // [c][i]
    __shared__ float t4s[28 * 9];       // [m][i]

    const int tid = threadIdx.x;
    const int b   = blockIdx.x;         // 0..55
    const int o   = b >> 5 ? 0 : 0;     // placeholder (computed below properly)
    const int og  = b / 28;             // group 0/1
    const int n   = b % 28;             // input height row
    (void)o;

    // --- Stage w2 transposed: w2[(j*7+k)*9 + i] -> w2t[i*224 + j*7 + k]
    #pragma unroll
    for (int idx = tid; idx < 9 * 224; idx += NTHREADS) {
        const int i = idx / 224;
        const int r = idx - i * 224;    // j*7 + k
        w2t[idx] = w2[r * 9 + i];
    }
    // --- Stage w1
    #pragma unroll
    for (int idx = tid; idx < 128 * 9; idx += NTHREADS) {
        w1s[idx] = w1[idx];
    }
    // --- Stage x row slab with zero halo
    #pragma unroll
    for (int idx = tid; idx < 32 * 34; idx += NTHREADS) {
        const int j  = idx / 34;
        const int mm = idx - j * 34;
        const int m  = mm - 3;
        float v = 0.0f;
        if (m >= 0 && m < 28)
            v = x[((og * 32 + j) * 28 + n) * 28 + m];
        xs[j][mm] = v;
    }
    __syncthreads();

    // --- t4: thread = (i, m). i = tid/28 keeps warps ~uniform in i:
    //     w2t reads broadcast across the warp, xs reads are consecutive m.
    if (tid < 252) {
        const int i = tid / 28;
        const int m = tid - i * 28;
        const float* __restrict__ wrow = &w2t[i * 224];
        float acc = 0.0f;
        #pragma unroll
        for (int j = 0; j < 32; ++j) {
            #pragma unroll
            for (int k = 0; k < 7; ++k) {
                acc = fmaf(xs[j][m + k], wrow[j * 7 + k], acc);
            }
        }
        t4s[m * 9 + i] = acc;
    }
    __syncthreads();

    // --- t5 + roll fused into the store index.
    const int nout = (n + 1) % 28;      // jnp.roll(y, +1, axis=2)
    #pragma unroll
    for (int idx = tid; idx < 128 * 28; idx += NTHREADS) {
        const int c = idx / 28;
        const int m = idx - c * 28;
        const float* __restrict__ t4m = &t4s[m * 9];
        const float* __restrict__ w1c = &w1s[c * 9];
        float acc = 0.0f;
        #pragma unroll
        for (int i = 0; i < 9; ++i) {
            acc = fmaf(t4m[i], w1c[i], acc);
        }
        out[((og * 128 + c) * 28 + nout) * 28 + m] = acc;
    }
}

extern "C" void kernel_launch(void* const* d_in, const int* in_sizes, int n_in,
                              void* d_out, int out_size) {
    const float* x  = (const float*)d_in[0];
    const float* w1 = (const float*)d_in[1];
    const float* w2 = (const float*)d_in[2];
    float* out = (float*)d_out;
    (void)in_sizes; (void)n_in; (void)out_size;

    fused_unfold_einsum_kernel<<<56, NTHREADS>>>(x, w1, w2, out);
}